// round 11
// baseline (speedup 1.0000x reference)
#include <cuda_runtime.h>
#include <stdint.h>

#define N_OBJ 16384
#define N_DIM 4096
#define HB    4096              // stored fine bins; C > HB -> exact slow path
#define HW    (HB / 2)          // u32 words per dim (u16-packed pairs)
#define INV_SQRT2 0.70710678118654752440f
// x < XCUT -> true p >= 0.05016 > 0.05f + approx-err: sentinel guaranteed,
// identical to evaluating the full approximation.
#define XCUT  1.1620f

// Zero-initialized at module load; phase2 restores zeros after each use, so
// every kernel_launch (and every graph replay) sees a zeroed histogram.
__device__ uint32_t g_hist[(size_t)N_DIM * HW];   // 32 MB, L2-resident
__device__ uint32_t g_cnt[N_DIM];

// thr(j) = 0.05f * float32((j+1)/16384)
__device__ __forceinline__ float thr(int j) {
    return __fmul_rn(0.05f, (float)(j + 1) * 6.103515625e-05f);
}

// ---------------- phase 1: stream -> mask -> RED into global hist ---------
// Block 256 = (32 tx=dim, 8 ty=obj), 8 objs/thread -> tile 32 dims x 64 objs.
__global__ void __launch_bounds__(256) phase1_kernel(
        const float* __restrict__ q_mu, const float* __restrict__ q_var) {
    __shared__ uint32_t s_cnt[32];

    const int tid = threadIdx.x, tx = tid & 31, ty = tid >> 5;
    const int d = blockIdx.x * 32 + tx;
    const size_t base = (size_t)(blockIdx.y * 64 + ty) * N_DIM + d;

    if (tid < 32) s_cnt[tid] = 0;
    __syncthreads();

    // Load 16 values (MLP), compute x = (mu/v)/sqrt2, build active mask.
    float xx[8];
    uint32_t mask = 0;
    {
        float mm[8], vv[8];
        #pragma unroll
        for (int r = 0; r < 8; r++) {
            mm[r] = __ldcs(q_mu  + base + (size_t)(r * 8) * N_DIM);
            vv[r] = __ldcs(q_var + base + (size_t)(r * 8) * N_DIM);
        }
        #pragma unroll
        for (int r = 0; r < 8; r++) {
            float x = __fdividef(mm[r], vv[r]) * INV_SQRT2;
            xx[r] = x;
            if (x >= XCUT) mask |= (1u << r);
        }
    }

    // Full erfc+bin path only for active elements (~1.3 avg, warp-max ~4-5).
    uint32_t* hrow = g_hist + (size_t)d * HW;
    uint32_t cnt = 0;
    while (mask) {
        int r = __ffs(mask) - 1;
        mask &= mask - 1;
        float xc = xx[0];                    // select-chain fetch (no spill)
        #pragma unroll
        for (int q = 1; q < 8; q++) xc = (r == q) ? xx[q] : xc;

        // xc >= 1.162 > 1: no clamp needed. p = 0.5*erfc(xc).
        float h = xc * xc;                   // exp(-x^2), Dekker-corrected
        float l = fmaf(xc, xc, -h);
        float e = __expf(-h);
        e = fmaf(-l, e, e);
        float den = fmaf(0.3275911f, xc, 1.0f);   // A&S 7.1.26, err<=1.5e-7
        float t = __fdividef(1.0f, den);
        float poly = fmaf(t, 1.061405429f, -1.453152027f);
        poly = fmaf(t, poly, 1.421413741f);
        poly = fmaf(t, poly, -0.284496736f);
        poly = fmaf(t, poly, 0.254829592f);
        float p = 0.5f * t * poly * e;

        if (p <= 0.05f) {                    // thr(16383) == 0.05f exactly
            int j = (int)ceilf(p * 327680.0f) - 1;    // thresholds uniform in p
            j = min(max(j, 0), N_OBJ - 1);
            while (j > 0 && p <= thr(j - 1)) --j;     // fp fixup, ~0-1 iters
            while (j < N_OBJ - 1 && p > thr(j)) ++j;
            cnt++;
            if (j < HB)
                atomicAdd(&hrow[j >> 1], 1u << ((j & 1) << 4));  // RED, u16 pair
        }
    }

    if (cnt) atomicAdd(&s_cnt[tx], cnt);     // lane==dim: conflict-free ATOMS
    __syncthreads();
    if (tid < 32 && s_cnt[tid])
        atomicAdd(&g_cnt[blockIdx.x * 32 + tid], s_cnt[tid]);    // RED
}

// ---------------- phase 2: scan L2-resident hist, then re-zero it ---------
__global__ void __launch_bounds__(1024) phase2_kernel(
        const float* __restrict__ q_mu, const float* __restrict__ q_var,
        float* __restrict__ out) {
    __shared__ uint32_t warp_part[32];
    __shared__ uint32_t red_cnt[32];
    __shared__ int      red_min[32];
    __shared__ uint32_t s_slow[N_OBJ / 2];   // 32 KB, slow path only

    const int tid = threadIdx.x, lane = tid & 31, wid = tid >> 5;
    const int d = blockIdx.x;
    const uint32_t C = g_cnt[d];
    __syncthreads();                          // all read C before tid0 clears
    if (tid == 0) g_cnt[d] = 0;               // restore invariant

    if (C == 0) { if (tid == 0) out[d] = 0.0f; return; }  // row already zero

    uint32_t count = 0;
    int firstj = 0x7fffffff;
    uint32_t* hrow = g_hist + (size_t)d * HW;

    if (C <= (uint32_t)HB) {
        // fast path: single 4096-bin scan, 4 bins/thread, coalesced u64 loads
        uint2 w = ((uint2*)hrow)[tid];
        ((uint2*)hrow)[tid] = make_uint2(0u, 0u);    // restore invariant
        uint32_t b0 = w.x & 0xFFFFu, b1 = w.x >> 16;
        uint32_t b2 = w.y & 0xFFFFu, b3 = w.y >> 16;
        uint32_t s4 = b0 + b1 + b2 + b3;

        uint32_t x = s4;
        #pragma unroll
        for (int o = 1; o < 32; o <<= 1) {
            uint32_t y = __shfl_up_sync(0xffffffffu, x, o);
            if (lane >= o) x += y;
        }
        if (lane == 31) warp_part[wid] = x;
        __syncthreads();
        if (wid == 0) {
            uint32_t ww = warp_part[lane];
            #pragma unroll
            for (int o = 1; o < 32; o <<= 1) {
                uint32_t y = __shfl_up_sync(0xffffffffu, ww, o);
                if (lane >= o) ww += y;
            }
            warp_part[lane] = ww;
        }
        __syncthreads();

        uint32_t cum = x - s4 + (wid > 0 ? warp_part[wid - 1] : 0u);
        int jb = tid * 4;
        cum += b0; if (cum >= (uint32_t)(jb + 1)) { count++; firstj = jb; }
        cum += b1; if (cum >= (uint32_t)(jb + 2)) { count++; firstj = min(firstj, jb + 1); }
        cum += b2; if (cum >= (uint32_t)(jb + 3)) { count++; firstj = min(firstj, jb + 2); }
        cum += b3; if (cum >= (uint32_t)(jb + 4)) { count++; firstj = min(firstj, jb + 3); }
    } else {
        // slow path (C > 4096: >25-sigma event): exact full-range recompute.
        for (int k = tid; k < HW; k += 1024) hrow[k] = 0;   // restore invariant
        for (int k = tid; k < N_OBJ / 2; k += 1024) s_slow[k] = 0;
        __syncthreads();
        for (int k = tid; k < N_OBJ; k += 1024) {
            float m = q_mu[(size_t)k * N_DIM + d];
            float v = q_var[(size_t)k * N_DIM + d];
            float x = __fdividef(m, v) * INV_SQRT2;
            if (x < XCUT) continue;
            float h = x * x;
            float l = fmaf(x, x, -h);
            float e = __expf(-h);
            e = fmaf(-l, e, e);
            float den = fmaf(0.3275911f, x, 1.0f);
            float t = __fdividef(1.0f, den);
            float poly = fmaf(t, 1.061405429f, -1.453152027f);
            poly = fmaf(t, poly, 1.421413741f);
            poly = fmaf(t, poly, -0.284496736f);
            poly = fmaf(t, poly, 0.254829592f);
            float p = 0.5f * t * poly * e;
            if (p <= 0.05f) {
                int j = (int)ceilf(p * 327680.0f) - 1;
                j = min(max(j, 0), N_OBJ - 1);
                while (j > 0 && p <= thr(j - 1)) --j;
                while (j < N_OBJ - 1 && p > thr(j)) ++j;
                atomicAdd(&s_slow[j >> 1], 1u << ((j & 1) << 4));
            }
        }
        __syncthreads();
        uint32_t carry = 0;
        for (int c = 0; c < 16; ++c) {
            int j = c * 1024 + tid;
            uint32_t x = (s_slow[j >> 1] >> ((j & 1) << 4)) & 0xFFFFu;
            #pragma unroll
            for (int o = 1; o < 32; o <<= 1) {
                uint32_t y = __shfl_up_sync(0xffffffffu, x, o);
                if (lane >= o) x += y;
            }
            if (lane == 31) warp_part[wid] = x;
            __syncthreads();
            if (wid == 0) {
                uint32_t ww = warp_part[lane];
                #pragma unroll
                for (int o = 1; o < 32; o <<= 1) {
                    uint32_t y = __shfl_up_sync(0xffffffffu, ww, o);
                    if (lane >= o) ww += y;
                }
                warp_part[lane] = ww;
            }
            __syncthreads();
            uint32_t incl = x + (wid > 0 ? warp_part[wid - 1] : 0u) + carry;
            if (incl >= (uint32_t)(j + 1)) { count++; firstj = min(firstj, j); }
            __syncthreads();
            carry += warp_part[31];
            __syncthreads();
        }
    }

    // block reduce (sum count, min firstj)
    #pragma unroll
    for (int o = 16; o > 0; o >>= 1) {
        count += __shfl_down_sync(0xffffffffu, count, o);
        firstj = min(firstj, __shfl_down_sync(0xffffffffu, firstj, o));
    }
    if (lane == 0) { red_cnt[wid] = count; red_min[wid] = firstj; }
    __syncthreads();
    if (wid == 0) {
        uint32_t cc = red_cnt[lane];
        int mm = red_min[lane];
        #pragma unroll
        for (int o = 16; o > 0; o >>= 1) {
            cc += __shfl_down_sync(0xffffffffu, cc, o);
            mm = min(mm, __shfl_down_sync(0xffffffffu, mm, o));
        }
        if (lane == 0)
            out[d] = (float)(cc + ((mm == 0x7fffffff) ? 0u : (uint32_t)mm));
    }
}

extern "C" void kernel_launch(void* const* d_in, const int* in_sizes, int n_in,
                              void* d_out, int out_size) {
    const float* q_mu  = (const float*)d_in[0];
    const float* q_var = (const float*)d_in[1];
    float* out = (float*)d_out;

    dim3 g1(N_DIM / 32, N_OBJ / 64);
    phase1_kernel<<<g1, 256>>>(q_mu, q_var);
    phase2_kernel<<<N_DIM, 1024>>>(q_mu, q_var, out);
}

// round 12
// speedup vs baseline: 1.7140x; 1.7140x over previous
#include <cuda_runtime.h>
#include <stdint.h>

#define N_OBJ 16384
#define N_DIM 4096
#define HB    4096              // stored fine bins; C > HB -> exact slow path
#define HW    (HB / 2)          // u32 words per dim (u16-packed pairs)
#define INV_SQRT2 0.70710678118654752440f
// x < XCUT -> true p >= 0.05016 > 0.05f + approx-err: sentinel guaranteed.
#define XCUT  1.1620f

__device__ uint32_t g_hist[(size_t)N_DIM * HW];   // 32 MB, L2-resident
__device__ uint32_t g_cnt[N_DIM];

// thr(j) = 0.05f * float32((j+1)/16384)
__device__ __forceinline__ float thr(int j) {
    return __fmul_rn(0.05f, (float)(j + 1) * 6.103515625e-05f);
}

// ---------------- zero: hist + counts (every launch; graph-safe) ----------
__global__ void zero_kernel() {
    size_t i = (size_t)blockIdx.x * 1024 + threadIdx.x;     // 2048*1024 threads
    ((uint4*)g_hist)[i] = make_uint4(0u, 0u, 0u, 0u);       // 8.4M words exactly
    if (i < N_DIM) g_cnt[i] = 0;
}

// ---------------- phase 1: stream -> mask -> RED into global hist ---------
// Block 256 = (32 tx=dim, 8 ty=obj), 8 objs/thread -> tile 32 dims x 64 objs.
__global__ void __launch_bounds__(256) phase1_kernel(
        const float* __restrict__ q_mu, const float* __restrict__ q_var) {
    __shared__ uint32_t s_cnt[32];

    const int tid = threadIdx.x, tx = tid & 31, ty = tid >> 5;
    const int d = blockIdx.x * 32 + tx;
    const size_t base = (size_t)(blockIdx.y * 64 + ty) * N_DIM + d;

    if (tid < 32) s_cnt[tid] = 0;
    __syncthreads();

    // Load 16 values (MLP), compute x = (mu/v)/sqrt2, build active mask.
    float xx[8];
    uint32_t mask = 0;
    {
        float mm[8], vv[8];
        #pragma unroll
        for (int r = 0; r < 8; r++) {
            mm[r] = __ldcs(q_mu  + base + (size_t)(r * 8) * N_DIM);
            vv[r] = __ldcs(q_var + base + (size_t)(r * 8) * N_DIM);
        }
        #pragma unroll
        for (int r = 0; r < 8; r++) {
            float x = __fdividef(mm[r], vv[r]) * INV_SQRT2;
            xx[r] = x;
            if (x >= XCUT) mask |= (1u << r);
        }
    }

    // Full erfc+bin path only for active elements (~1.3 avg per thread).
    uint32_t* hrow = g_hist + (size_t)d * HW;
    uint32_t cnt = 0;
    while (mask) {
        int r = __ffs(mask) - 1;
        mask &= mask - 1;
        float xc = xx[0];                    // select-chain fetch (no spill)
        #pragma unroll
        for (int q = 1; q < 8; q++) xc = (r == q) ? xx[q] : xc;

        // xc >= 1.162 > 1: no clamp needed. p = 0.5*erfc(xc).
        float h = xc * xc;                   // exp(-x^2), Dekker-corrected
        float l = fmaf(xc, xc, -h);
        float e = __expf(-h);
        e = fmaf(-l, e, e);
        float den = fmaf(0.3275911f, xc, 1.0f);   // A&S 7.1.26, err<=1.5e-7
        float t = __fdividef(1.0f, den);
        float poly = fmaf(t, 1.061405429f, -1.453152027f);
        poly = fmaf(t, poly, 1.421413741f);
        poly = fmaf(t, poly, -0.284496736f);
        poly = fmaf(t, poly, 0.254829592f);
        float p = 0.5f * t * poly * e;

        if (p <= 0.05f) {                    // thr(16383) == 0.05f exactly
            int j = (int)ceilf(p * 327680.0f) - 1;    // thresholds uniform in p
            j = min(max(j, 0), N_OBJ - 1);
            while (j > 0 && p <= thr(j - 1)) --j;     // fp fixup, ~0-1 iters
            while (j < N_OBJ - 1 && p > thr(j)) ++j;
            cnt++;
            if (j < HB)
                atomicAdd(&hrow[j >> 1], 1u << ((j & 1) << 4));  // RED, u16 pair
        }
    }

    if (cnt) atomicAdd(&s_cnt[tx], cnt);     // lane==dim: conflict-free ATOMS
    __syncthreads();
    if (tid < 32 && s_cnt[tid])
        atomicAdd(&g_cnt[blockIdx.x * 32 + tid], s_cnt[tid]);    // RED
}

// ---------------- phase 2: read-only scan of L2-resident hist (R10) -------
__global__ void __launch_bounds__(1024) phase2_kernel(
        const float* __restrict__ q_mu, const float* __restrict__ q_var,
        float* __restrict__ out) {
    __shared__ uint32_t warp_part[32];
    __shared__ uint32_t red_cnt[32];
    __shared__ int      red_min[32];
    __shared__ uint32_t s_slow[N_OBJ / 2];   // 32 KB, slow path only

    const int tid = threadIdx.x, lane = tid & 31, wid = tid >> 5;
    const int d = blockIdx.x;
    const uint32_t C = g_cnt[d];

    if (C == 0) { if (tid == 0) out[d] = 0.0f; return; }

    uint32_t count = 0;
    int firstj = 0x7fffffff;

    if (C <= (uint32_t)HB) {
        // fast path: single 4096-bin scan, 4 bins/thread, coalesced
        const uint32_t* hw = g_hist + (size_t)d * HW + tid * 2;
        uint32_t w0 = hw[0], w1 = hw[1];
        uint32_t b0 = w0 & 0xFFFFu, b1 = w0 >> 16;
        uint32_t b2 = w1 & 0xFFFFu, b3 = w1 >> 16;
        uint32_t s4 = b0 + b1 + b2 + b3;

        uint32_t x = s4;
        #pragma unroll
        for (int o = 1; o < 32; o <<= 1) {
            uint32_t y = __shfl_up_sync(0xffffffffu, x, o);
            if (lane >= o) x += y;
        }
        if (lane == 31) warp_part[wid] = x;
        __syncthreads();
        if (wid == 0) {
            uint32_t ww = warp_part[lane];
            #pragma unroll
            for (int o = 1; o < 32; o <<= 1) {
                uint32_t y = __shfl_up_sync(0xffffffffu, ww, o);
                if (lane >= o) ww += y;
            }
            warp_part[lane] = ww;
        }
        __syncthreads();

        uint32_t cum = x - s4 + (wid > 0 ? warp_part[wid - 1] : 0u);
        int jb = tid * 4;
        cum += b0; if (cum >= (uint32_t)(jb + 1)) { count++; firstj = jb; }
        cum += b1; if (cum >= (uint32_t)(jb + 2)) { count++; firstj = min(firstj, jb + 1); }
        cum += b2; if (cum >= (uint32_t)(jb + 3)) { count++; firstj = min(firstj, jb + 2); }
        cum += b3; if (cum >= (uint32_t)(jb + 4)) { count++; firstj = min(firstj, jb + 3); }
    } else {
        // slow path (C > 4096: >25-sigma event): exact full-range recompute.
        for (int k = tid; k < N_OBJ / 2; k += 1024) s_slow[k] = 0;
        __syncthreads();
        for (int k = tid; k < N_OBJ; k += 1024) {
            float m = q_mu[(size_t)k * N_DIM + d];
            float v = q_var[(size_t)k * N_DIM + d];
            float x = __fdividef(m, v) * INV_SQRT2;
            if (x < XCUT) continue;
            float h = x * x;
            float l = fmaf(x, x, -h);
            float e = __expf(-h);
            e = fmaf(-l, e, e);
            float den = fmaf(0.3275911f, x, 1.0f);
            float t = __fdividef(1.0f, den);
            float poly = fmaf(t, 1.061405429f, -1.453152027f);
            poly = fmaf(t, poly, 1.421413741f);
            poly = fmaf(t, poly, -0.284496736f);
            poly = fmaf(t, poly, 0.254829592f);
            float p = 0.5f * t * poly * e;
            if (p <= 0.05f) {
                int j = (int)ceilf(p * 327680.0f) - 1;
                j = min(max(j, 0), N_OBJ - 1);
                while (j > 0 && p <= thr(j - 1)) --j;
                while (j < N_OBJ - 1 && p > thr(j)) ++j;
                atomicAdd(&s_slow[j >> 1], 1u << ((j & 1) << 4));
            }
        }
        __syncthreads();
        uint32_t carry = 0;
        for (int c = 0; c < 16; ++c) {
            int j = c * 1024 + tid;
            uint32_t x = (s_slow[j >> 1] >> ((j & 1) << 4)) & 0xFFFFu;
            #pragma unroll
            for (int o = 1; o < 32; o <<= 1) {
                uint32_t y = __shfl_up_sync(0xffffffffu, x, o);
                if (lane >= o) x += y;
            }
            if (lane == 31) warp_part[wid] = x;
            __syncthreads();
            if (wid == 0) {
                uint32_t ww = warp_part[lane];
                #pragma unroll
                for (int o = 1; o < 32; o <<= 1) {
                    uint32_t y = __shfl_up_sync(0xffffffffu, ww, o);
                    if (lane >= o) ww += y;
                }
                warp_part[lane] = ww;
            }
            __syncthreads();
            uint32_t incl = x + (wid > 0 ? warp_part[wid - 1] : 0u) + carry;
            if (incl >= (uint32_t)(j + 1)) { count++; firstj = min(firstj, j); }
            __syncthreads();
            carry += warp_part[31];
            __syncthreads();
        }
    }

    // block reduce (sum count, min firstj)
    #pragma unroll
    for (int o = 16; o > 0; o >>= 1) {
        count += __shfl_down_sync(0xffffffffu, count, o);
        firstj = min(firstj, __shfl_down_sync(0xffffffffu, firstj, o));
    }
    if (lane == 0) { red_cnt[wid] = count; red_min[wid] = firstj; }
    __syncthreads();
    if (wid == 0) {
        uint32_t cc = red_cnt[lane];
        int mm = red_min[lane];
        #pragma unroll
        for (int o = 16; o > 0; o >>= 1) {
            cc += __shfl_down_sync(0xffffffffu, cc, o);
            mm = min(mm, __shfl_down_sync(0xffffffffu, mm, o));
        }
        if (lane == 0)
            out[d] = (float)(cc + ((mm == 0x7fffffff) ? 0u : (uint32_t)mm));
    }
}

extern "C" void kernel_launch(void* const* d_in, const int* in_sizes, int n_in,
                              void* d_out, int out_size) {
    const float* q_mu  = (const float*)d_in[0];
    const float* q_var = (const float*)d_in[1];
    float* out = (float*)d_out;

    zero_kernel<<<(N_DIM * HW / 4) / 1024, 1024>>>();        // 2048 blocks
    dim3 g1(N_DIM / 32, N_OBJ / 64);
    phase1_kernel<<<g1, 256>>>(q_mu, q_var);
    phase2_kernel<<<N_DIM, 1024>>>(q_mu, q_var, out);
}